// round 1
// baseline (speedup 1.0000x reference)
#include <cuda_runtime.h>
#include <math.h>

// ---------------------------------------------------------------------------
// Problem constants
//   x:(4,2,256,256)  h:(4,128,256,256)  y1:(4,512,256,256)
//   spectral scratch: (512 images, 256 rows, 129 cols) complex
// ---------------------------------------------------------------------------
#define NPOS   65536              // 256*256
#define BATCH  4
#define DIM    128
#define HID    512
#define LAYERS 4
#define WH     129

// ------------------------- device scratch (static; no runtime alloc) -------
__device__ float  g_h [(size_t)BATCH * DIM * NPOS];     // 128 MB
__device__ float  g_y1[(size_t)BATCH * HID * NPOS];     // 512 MB
__device__ float  g_x1[(size_t)BATCH * DIM * NPOS];     // 128 MB
__device__ float2 g_fft[(size_t)BATCH * DIM * 256 * WH];// 135 MB
__device__ float2 g_tw[256];                            // twiddle table

// ---------------------------------------------------------------------------
// Twiddle init: g_tw[half + p] = exp(-2*pi*i * p / (2*half)),  half=1..128
// ---------------------------------------------------------------------------
__global__ void init_tw_kernel() {
    int t = threadIdx.x;                 // 0..255
    if (t == 0) { g_tw[0] = make_float2(1.f, 0.f); return; }
    int half = 1 << (31 - __clz(t));
    int p    = t - half;
    int len  = half << 1;
    double th = -2.0 * 3.14159265358979323846 * (double)p / (double)len;
    g_tw[t] = make_float2((float)cos(th), (float)sin(th));
}

// ---------------------------------------------------------------------------
// Encoder: h = (x @ enc_w^T + enc_b) * 8 + pos_emb
// ---------------------------------------------------------------------------
__global__ void encode_kernel(const float* __restrict__ x,
                              const float* __restrict__ ew,
                              const float* __restrict__ eb,
                              const float* __restrict__ pos) {
    int idx = blockIdx.x * 256 + threadIdx.x;          // (b,o,p) flattened
    int p = idx & (NPOS - 1);
    int o = (idx >> 16) & 127;
    int b = idx >> 23;
    float x0 = x[((b * 2 + 0) << 16) + p];
    float x1 = x[((b * 2 + 1) << 16) + p];
    float v = fmaf(x0, ew[o * 2], fmaf(x1, ew[o * 2 + 1], eb[o])) * 8.0f
              + pos[(o << 16) + p];
    g_h[idx] = v;
}

// ---------------------------------------------------------------------------
// Decoder: out = (h @ dec_w^T + dec_b) / 8
// ---------------------------------------------------------------------------
__global__ void decode_kernel(const float* __restrict__ dw,
                              const float* __restrict__ db,
                              float* __restrict__ out) {
    int idx = blockIdx.x * 256 + threadIdx.x;          // (b,p) flattened
    int p = idx & (NPOS - 1);
    int b = idx >> 16;
    const float* hb = g_h + ((size_t)b << 23);
    float a0 = 0.f, a1 = 0.f;
#pragma unroll 8
    for (int c = 0; c < 128; c++) {
        float hv = hb[(c << 16) + p];
        a0 = fmaf(hv, dw[c], a0);
        a1 = fmaf(hv, dw[128 + c], a1);
    }
    out[((b * 2 + 0) << 16) + p] = (a0 + db[0]) * 0.125f;
    out[((b * 2 + 1) << 16) + p] = (a1 + db[1]) * 0.125f;
}

// ---------------------------------------------------------------------------
// SGEMM  Y[M,NPOS] = W[M,K] @ X[K,NPOS] (+bias, optional SiLU, optional +=Y)
// Block tile 128x128, BK=8, 256 threads, 8x8 micro, packed f32x2 FMAs.
// ---------------------------------------------------------------------------
typedef unsigned long long u64;
__device__ __forceinline__ u64 pk2(float lo, float hi) {
    u64 r; asm("mov.b64 %0, {%1, %2};" : "=l"(r) : "f"(lo), "f"(hi)); return r;
}
__device__ __forceinline__ void upk2(u64 v, float& lo, float& hi) {
    asm("mov.b64 {%0, %1}, %2;" : "=f"(lo), "=f"(hi) : "l"(v));
}
__device__ __forceinline__ void fma2(u64& d, u64 a, u64 b) {
    asm("fma.rn.f32x2 %0, %1, %2, %0;" : "+l"(d) : "l"(a), "l"(b));
}

template <bool SILU, bool RES>
__global__ __launch_bounds__(256) void gemm_kernel(
    const float* __restrict__ W, const float* __restrict__ bias,
    const float* __restrict__ X, float* __restrict__ Y, int M, int K) {
    __shared__ float As[8][128];
    __shared__ float Bs[8][128];
    const int tid = threadIdx.x;
    const int n0 = blockIdx.x * 128;
    const int m0 = blockIdx.y * 128;
    const int b  = blockIdx.z;
    const float* Xb = X + (size_t)b * K * NPOS;
    float*       Yb = Y + (size_t)b * M * NPOS;

    const int aRow = tid >> 1, aCol = (tid & 1) * 4;
    const int bRow = tid >> 5, bCol = (tid & 31) * 4;
    const int ty = tid >> 4, tx = tid & 15;

    u64 acc[8][4];
#pragma unroll
    for (int i = 0; i < 8; i++)
#pragma unroll
        for (int j = 0; j < 4; j++) acc[i][j] = 0ull;

    const float* wp = W + (size_t)(m0 + aRow) * K + aCol;
    const float* xp = Xb + (size_t)bRow * NPOS + n0 + bCol;

    for (int kt = 0; kt < K; kt += 8) {
        float4 a4 = *(const float4*)(wp + kt);
        As[aCol + 0][aRow] = a4.x;
        As[aCol + 1][aRow] = a4.y;
        As[aCol + 2][aRow] = a4.z;
        As[aCol + 3][aRow] = a4.w;
        float4 b4 = *(const float4*)(xp + (size_t)kt * NPOS);
        *(float4*)&Bs[bRow][bCol] = b4;
        __syncthreads();
#pragma unroll
        for (int k = 0; k < 8; k++) {
            float4 bb0 = *(const float4*)&Bs[k][tx * 8];
            float4 bb1 = *(const float4*)&Bs[k][tx * 8 + 4];
            u64 rb0 = pk2(bb0.x, bb0.y), rb1 = pk2(bb0.z, bb0.w);
            u64 rb2 = pk2(bb1.x, bb1.y), rb3 = pk2(bb1.z, bb1.w);
            float4 aa0 = *(const float4*)&As[k][ty * 8];
            float4 aa1 = *(const float4*)&As[k][ty * 8 + 4];
            float av[8] = {aa0.x, aa0.y, aa0.z, aa0.w, aa1.x, aa1.y, aa1.z, aa1.w};
#pragma unroll
            for (int i = 0; i < 8; i++) {
                u64 ra = pk2(av[i], av[i]);
                fma2(acc[i][0], ra, rb0);
                fma2(acc[i][1], ra, rb1);
                fma2(acc[i][2], ra, rb2);
                fma2(acc[i][3], ra, rb3);
            }
        }
        __syncthreads();
    }

#pragma unroll
    for (int i = 0; i < 8; i++) {
        int m = m0 + ty * 8 + i;
        float bv = bias[m];
        float v[8];
        upk2(acc[i][0], v[0], v[1]);
        upk2(acc[i][1], v[2], v[3]);
        upk2(acc[i][2], v[4], v[5]);
        upk2(acc[i][3], v[6], v[7]);
        float* yp = Yb + (size_t)m * NPOS + n0 + tx * 8;
#pragma unroll
        for (int j = 0; j < 8; j++) {
            float t = v[j] + bv;
            if (SILU) t = t / (1.f + expf(-t));   // silu = x*sigmoid(x)
            v[j] = t;
        }
        if (RES) {
            float4 r0 = *(const float4*)(yp);
            float4 r1 = *(const float4*)(yp + 4);
            v[0] += r0.x; v[1] += r0.y; v[2] += r0.z; v[3] += r0.w;
            v[4] += r1.x; v[5] += r1.y; v[6] += r1.z; v[7] += r1.w;
        }
        *(float4*)(yp)     = make_float4(v[0], v[1], v[2], v[3]);
        *(float4*)(yp + 4) = make_float4(v[4], v[5], v[6], v[7]);
    }
}

// ---------------------------------------------------------------------------
// 256-point radix-2 DIT FFT in shared memory. 128 threads, input already
// bit-reversed. Forward uses table as stored (e^{-i}); inverse conjugates.
// ---------------------------------------------------------------------------
template <bool INV>
__device__ __forceinline__ void fft256(float2* s, int tid) {
#pragma unroll
    for (int st = 1; st <= 8; st++) {
        const int half = 1 << (st - 1);
        int p = tid & (half - 1);
        int i = ((tid >> (st - 1)) << st) | p;
        float2 w = g_tw[half + p];
        float wx = w.x;
        float wy = INV ? -w.y : w.y;
        float2 u = s[i], v = s[i + half];
        float tr = v.x * wx - v.y * wy;
        float ti = v.x * wy + v.y * wx;
        s[i]        = make_float2(u.x + tr, u.y + ti);
        s[i + half] = make_float2(u.x - tr, u.y - ti);
        __syncthreads();
    }
}
__device__ __forceinline__ int brev8(int i) { return __brev(i) >> 24; }

// Pass 1: forward FFT along rows (real input), keep bins 0..128.
__global__ __launch_bounds__(128) void fft_rows_fwd(const float* __restrict__ in,
                                                    float2* __restrict__ out) {
    __shared__ float  rb[256];
    __shared__ float2 s[256];
    int tid = threadIdx.x;
    size_t img = blockIdx.y;
    int y = blockIdx.x;
    const float* src = in + (img << 16) + (y << 8);
    rb[tid] = src[tid];
    rb[tid + 128] = src[tid + 128];
    __syncthreads();
    s[tid]       = make_float2(rb[brev8(tid)], 0.f);
    s[tid + 128] = make_float2(rb[brev8(tid + 128)], 0.f);
    __syncthreads();
    fft256<false>(s, tid);
    float2* dst = out + img * (256 * WH) + (size_t)y * WH;
    for (int k = tid; k < WH; k += 128) dst[k] = s[k];
}

// Pass 2 (fused): fwd FFT down columns -> filter*mask*(1/65536) -> inv FFT.
__global__ __launch_bounds__(128) void fft_cols_filter(float2* __restrict__ data,
                                                       const float* __restrict__ mags,
                                                       const float* __restrict__ phs) {
    __shared__ float2 sp[256];
    __shared__ float2 s[256];
    int tid = threadIdx.x;
    int kx = blockIdx.x;              // 0..128
    size_t img = blockIdx.y;          // b*128 + c
    int c = (int)(img & 127);
    float2* col = data + img * (256 * WH) + kx;
    sp[tid]       = col[(size_t)tid * WH];
    sp[tid + 128] = col[(size_t)(tid + 128) * WH];
    __syncthreads();
    s[tid]       = sp[brev8(tid)];
    s[tid + 128] = sp[brev8(tid + 128)];
    __syncthreads();
    fft256<false>(s, tid);
    // filter: filt = sigmoid(mag)*exp(i*phase)/65536 on kx^2+ky^2<=128^2, else 0
#pragma unroll
    for (int it = 0; it < 2; it++) {
        int idx = tid + it * 128;     // ky index in natural FFT order
        int kyab = (idx < 128) ? idx : 256 - idx;
        float2 v;
        if (kx * kx + kyab * kyab <= 16384) {
            int off = (c * 256 + idx) * WH + kx;
            float sg = 1.f / (1.f + expf(-mags[off])) * (1.f / 65536.f);
            float sn, cs;
            sincosf(phs[off], &sn, &cs);
            float fr = sg * cs, fi = sg * sn;
            float2 u = s[idx];
            v = make_float2(u.x * fr - u.y * fi, u.x * fi + u.y * fr);
        } else {
            v = make_float2(0.f, 0.f);
        }
        sp[idx] = v;
    }
    __syncthreads();
    s[tid]       = sp[brev8(tid)];
    s[tid + 128] = sp[brev8(tid + 128)];
    __syncthreads();
    fft256<true>(s, tid);
    col[(size_t)tid * WH]         = s[tid];
    col[(size_t)(tid + 128) * WH] = s[tid + 128];
}

// Pass 3: inverse FFT along rows (Hermitian extension), real output.
__global__ __launch_bounds__(128) void fft_rows_inv(const float2* __restrict__ in,
                                                    float* __restrict__ out) {
    __shared__ float2 sp[256];   // bins 0..128 valid
    __shared__ float2 s[256];
    int tid = threadIdx.x;
    size_t img = blockIdx.y;
    int y = blockIdx.x;
    const float2* src = in + img * (256 * WH) + (size_t)y * WH;
    for (int k = tid; k < WH; k += 128) sp[k] = src[k];
    __syncthreads();
    int r0 = brev8(tid), r1 = brev8(tid + 128);
    float2 e0 = (r0 <= 128) ? sp[r0] : make_float2(sp[256 - r0].x, -sp[256 - r0].y);
    float2 e1 = (r1 <= 128) ? sp[r1] : make_float2(sp[256 - r1].x, -sp[256 - r1].y);
    s[tid] = e0;
    s[tid + 128] = e1;
    __syncthreads();
    fft256<true>(s, tid);
    float* dst = out + (img << 16) + (y << 8);
    dst[tid]       = s[tid].x;          // imag parts of bins 0/128 only feed
    dst[tid + 128] = s[tid + 128].x;    // the discarded imaginary output
}

// ---------------------------------------------------------------------------
// Launch
// ---------------------------------------------------------------------------
extern "C" void kernel_launch(void* const* d_in, const int* in_sizes, int n_in,
                              void* d_out, int out_size) {
    const float* x   = (const float*)d_in[0];
    const float* ew  = (const float*)d_in[1];
    const float* eb  = (const float*)d_in[2];
    const float* pos = (const float*)d_in[3];
    const float* w1  = (const float*)d_in[4];
    const float* b1  = (const float*)d_in[5];
    const float* w2  = (const float*)d_in[6];
    const float* b2  = (const float*)d_in[7];
    const float* mg  = (const float*)d_in[8];
    const float* ph  = (const float*)d_in[9];
    const float* ow  = (const float*)d_in[10];
    const float* ob  = (const float*)d_in[11];
    const float* dw  = (const float*)d_in[12];
    const float* db  = (const float*)d_in[13];
    float* out = (float*)d_out;

    void *vh, *vy, *vx, *vf;
    cudaGetSymbolAddress(&vh, g_h);
    cudaGetSymbolAddress(&vy, g_y1);
    cudaGetSymbolAddress(&vx, g_x1);
    cudaGetSymbolAddress(&vf, g_fft);
    float*  H  = (float*)vh;
    float*  Y1 = (float*)vy;
    float*  X1 = (float*)vx;
    float2* FT = (float2*)vf;

    init_tw_kernel<<<1, 256>>>();
    encode_kernel<<<(BATCH * DIM * NPOS) / 256, 256>>>(x, ew, eb, pos);

    const int specStride = DIM * 256 * WH;   // per-layer filter stride
    for (int l = 0; l < LAYERS; l++) {
        // mlp: h -> 512 (SiLU) -> 128
        gemm_kernel<true, false><<<dim3(512, 4, 4), 256>>>(
            w1 + (size_t)l * HID * DIM, b1 + l * HID, H, Y1, HID, DIM);
        gemm_kernel<false, false><<<dim3(512, 1, 4), 256>>>(
            w2 + (size_t)l * DIM * HID, b2 + l * DIM, Y1, X1, DIM, HID);
        // spectral conv
        fft_rows_fwd<<<dim3(256, BATCH * DIM), 128>>>(X1, FT);
        fft_cols_filter<<<dim3(WH, BATCH * DIM), 128>>>(
            FT, mg + (size_t)l * specStride, ph + (size_t)l * specStride);
        fft_rows_inv<<<dim3(256, BATCH * DIM), 128>>>(FT, X1);
        // oxo conv + residual into h
        gemm_kernel<false, true><<<dim3(512, 1, 4), 256>>>(
            ow + (size_t)l * DIM * DIM, ob + l * DIM, X1, H, DIM, DIM);
    }

    decode_kernel<<<(BATCH * NPOS) / 256, 256>>>(dw, db, out);
}

// round 5
// speedup vs baseline: 1.1890x; 1.1890x over previous
#include <cuda_runtime.h>
#include <cuda_bf16.h>
#include <math.h>
#include <stdint.h>

// ---------------------------------------------------------------------------
// Problem constants
// ---------------------------------------------------------------------------
#define NPOS   65536              // 256*256
#define BATCH  4
#define DIM    128
#define HID    512
#define LAYERS 4
#define WH     129

// ------------------------- device scratch (static; no runtime alloc) -------
__device__ float  g_h [(size_t)BATCH * DIM * NPOS];
__device__ float  g_y1[(size_t)BATCH * HID * NPOS];
__device__ float  g_x1[(size_t)BATCH * DIM * NPOS];
__device__ float2 g_fft[(size_t)BATCH * DIM * 256 * WH];
__device__ float2 g_tw[256];

// ---------------------------------------------------------------------------
// Twiddle init
// ---------------------------------------------------------------------------
__global__ void init_tw_kernel() {
    int t = threadIdx.x;
    if (t == 0) { g_tw[0] = make_float2(1.f, 0.f); return; }
    int half = 1 << (31 - __clz(t));
    int p    = t - half;
    int len  = half << 1;
    double th = -2.0 * 3.14159265358979323846 * (double)p / (double)len;
    g_tw[t] = make_float2((float)cos(th), (float)sin(th));
}

// ---------------------------------------------------------------------------
// Encoder / Decoder
// ---------------------------------------------------------------------------
__global__ void encode_kernel(const float* __restrict__ x,
                              const float* __restrict__ ew,
                              const float* __restrict__ eb,
                              const float* __restrict__ pos) {
    int idx = blockIdx.x * 256 + threadIdx.x;
    int p = idx & (NPOS - 1);
    int o = (idx >> 16) & 127;
    int b = idx >> 23;
    float x0 = x[((b * 2 + 0) << 16) + p];
    float x1 = x[((b * 2 + 1) << 16) + p];
    float v = fmaf(x0, ew[o * 2], fmaf(x1, ew[o * 2 + 1], eb[o])) * 8.0f
              + pos[(o << 16) + p];
    g_h[idx] = v;
}

__global__ void decode_kernel(const float* __restrict__ dw,
                              const float* __restrict__ db,
                              float* __restrict__ out) {
    int idx = blockIdx.x * 256 + threadIdx.x;
    int p = idx & (NPOS - 1);
    int b = idx >> 16;
    const float* hb = g_h + ((size_t)b << 23);
    float a0 = 0.f, a1 = 0.f;
#pragma unroll 8
    for (int c = 0; c < 128; c++) {
        float hv = hb[(c << 16) + p];
        a0 = fmaf(hv, dw[c], a0);
        a1 = fmaf(hv, dw[128 + c], a1);
    }
    out[((b * 2 + 0) << 16) + p] = (a0 + db[0]) * 0.125f;
    out[((b * 2 + 1) << 16) + p] = (a1 + db[1]) * 0.125f;
}

// ===========================================================================
// mma.sync (HMMA) bf16-split GEMM
//   Y[M,NPOS] = W[M,K] @ X[K,NPOS]  (+bias, opt SiLU, opt += residual Y)
//   fp32 -> bf16 hi/lo split, 3 passes (hh, hl, lh), fp32 accumulators.
//   CTA tile M=128 x N=128, K chunks of 128. 8 warps (2x4), warp tile 64x32.
// ===========================================================================

__device__ __forceinline__ uint32_t smem_u32(const void* p) {
    uint32_t a;
    asm("{ .reg .u64 t; cvta.to.shared.u64 t, %1; cvt.u32.u64 %0, t; }"
        : "=r"(a) : "l"(p));
    return a;
}

__device__ __forceinline__ void mma16816(float* c, const uint32_t* a, const uint32_t* b) {
    asm volatile("mma.sync.aligned.m16n8k16.row.col.f32.bf16.bf16.f32 "
        "{%0,%1,%2,%3}, {%4,%5,%6,%7}, {%8,%9}, {%0,%1,%2,%3};"
        : "+f"(c[0]), "+f"(c[1]), "+f"(c[2]), "+f"(c[3])
        : "r"(a[0]), "r"(a[1]), "r"(a[2]), "r"(a[3]), "r"(b[0]), "r"(b[1]));
}
__device__ __forceinline__ void ldsm4(uint32_t* r, uint32_t addr) {
    asm volatile("ldmatrix.sync.aligned.m8n8.x4.shared.b16 {%0,%1,%2,%3}, [%4];"
        : "=r"(r[0]), "=r"(r[1]), "=r"(r[2]), "=r"(r[3]) : "r"(addr));
}
__device__ __forceinline__ void ldsm2(uint32_t* r, uint32_t addr) {
    asm volatile("ldmatrix.sync.aligned.m8n8.x2.shared.b16 {%0,%1}, [%2];"
        : "=r"(r[0]), "=r"(r[1]) : "r"(addr));
}

// SMEM: padded rows of 136 bf16 (272 B) -> conflict-free ldmatrix.
#define ROWB   272
#define TILEB  (128 * ROWB)       // 34816 B
#define SA_HI  0
#define SA_LO  TILEB
#define SB_HI  (2 * TILEB)
#define SB_LO  (3 * TILEB)
#define SM_TOTAL (4 * TILEB)      // 139264 B

template <bool SILU, bool RES>
__global__ __launch_bounds__(256) void tc_gemm(
    const float* __restrict__ W, const float* __restrict__ bias,
    const float* __restrict__ X, float* __restrict__ Y, int K) {
    extern __shared__ char smem[];
    const int tid = threadIdx.x;
    const int wid = tid >> 5;
    const int lid = tid & 31;
    const uint32_t sb = smem_u32(smem);

    const int n0 = blockIdx.x * 128;
    const int m0 = blockIdx.y * 128;
    const int Mtot = gridDim.y * 128;
    const float* Xb = X + (size_t)blockIdx.z * K * NPOS;
    float*       Yb = Y + (size_t)blockIdx.z * Mtot * (size_t)NPOS;

    const int wm = wid >> 2;          // 0..1 : warp row (64 M each)
    const int wn = wid & 3;           // 0..3 : warp col (32 N each)

    // Per-lane ldmatrix byte offsets (within a tile)
    // A frag (x4): row = mbase + (l&15), k-half = (l>>4)
    uint32_t aoff[4], boff[4];
#pragma unroll
    for (int mf = 0; mf < 4; mf++)
        aoff[mf] = (uint32_t)((wm * 64 + mf * 16 + (lid & 15)) * ROWB + (lid >> 4) * 16);
#pragma unroll
    for (int nf = 0; nf < 4; nf++)
        boff[nf] = (uint32_t)((wn * 32 + nf * 8 + (lid & 7)) * ROWB + ((lid >> 3) & 1) * 16);

    float acc[4][4][4];
#pragma unroll
    for (int i = 0; i < 4; i++)
#pragma unroll
        for (int j = 0; j < 4; j++)
#pragma unroll
            for (int r = 0; r < 4; r++) acc[i][j][r] = 0.f;

    const int NC = K >> 7;
    for (int kc = 0; kc < NC; kc++) {
        // ---- W chunk [128 M, 128 K] -> A_hi / A_lo ----------------------
        for (int j = tid; j < 4096; j += 256) {
            int row = j >> 5, kk = (j & 31) * 4;
            float4 w4 = *(const float4*)(W + (size_t)(m0 + row) * K + kc * 128 + kk);
            __nv_bfloat162 hA = __floats2bfloat162_rn(w4.x, w4.y);
            __nv_bfloat162 hB = __floats2bfloat162_rn(w4.z, w4.w);
            __nv_bfloat162 lA = __floats2bfloat162_rn(w4.x - __bfloat162float(hA.x),
                                                      w4.y - __bfloat162float(hA.y));
            __nv_bfloat162 lB = __floats2bfloat162_rn(w4.z - __bfloat162float(hB.x),
                                                      w4.w - __bfloat162float(hB.y));
            int off = row * ROWB + kk * 2;
            *(uint2*)(smem + SA_HI + off) = make_uint2(*(uint32_t*)&hA, *(uint32_t*)&hB);
            *(uint2*)(smem + SA_LO + off) = make_uint2(*(uint32_t*)&lA, *(uint32_t*)&lB);
        }
        // ---- X chunk [128 K, 128 N] -> B = X^T [n][k] -------------------
        for (int j = tid; j < 8192; j += 256) {
            int n  = j & 127;
            int k2 = (j >> 7) * 2;
            const float* xp = Xb + (size_t)(kc * 128 + k2) * NPOS + n0 + n;
            float v0 = xp[0];
            float v1 = xp[NPOS];
            __nv_bfloat162 h01 = __floats2bfloat162_rn(v0, v1);
            __nv_bfloat162 l01 = __floats2bfloat162_rn(v0 - __bfloat162float(h01.x),
                                                       v1 - __bfloat162float(h01.y));
            int off = n * ROWB + k2 * 2;
            *(uint32_t*)(smem + SB_HI + off) = *(uint32_t*)&h01;
            *(uint32_t*)(smem + SB_LO + off) = *(uint32_t*)&l01;
        }
        __syncthreads();

        // ---- 8 k-steps of m16n8k16; 3 passes fused per step -------------
#pragma unroll
        for (int ks = 0; ks < 8; ks++) {
            const uint32_t ko = ks * 32;       // k0*2 bytes
            uint32_t ah[4][4], al[4][4], bh[4][2], bl[4][2];
#pragma unroll
            for (int mf = 0; mf < 4; mf++) {
                ldsm4(ah[mf], sb + SA_HI + aoff[mf] + ko);
                ldsm4(al[mf], sb + SA_LO + aoff[mf] + ko);
            }
#pragma unroll
            for (int nf = 0; nf < 4; nf++) {
                ldsm2(bh[nf], sb + SB_HI + boff[nf] + ko);
                ldsm2(bl[nf], sb + SB_LO + boff[nf] + ko);
            }
#pragma unroll
            for (int mf = 0; mf < 4; mf++)
#pragma unroll
                for (int nf = 0; nf < 4; nf++) {
                    mma16816(acc[mf][nf], ah[mf], bh[nf]);
                    mma16816(acc[mf][nf], ah[mf], bl[nf]);
                    mma16816(acc[mf][nf], al[mf], bh[nf]);
                }
        }
        __syncthreads();
    }

    // ---- epilogue: bias (+SiLU) (+residual), write fp32 ------------------
    const int q = lid >> 2;           // 0..7
    const int r2 = (lid & 3) * 2;     // 0,2,4,6
#pragma unroll
    for (int mf = 0; mf < 4; mf++) {
        int mrow0 = m0 + wm * 64 + mf * 16 + q;
        float bv0 = bias[mrow0];
        float bv1 = bias[mrow0 + 8];
        float* y0 = Yb + (size_t)mrow0 * NPOS + n0;
        float* y1 = y0 + (size_t)8 * NPOS;
#pragma unroll
        for (int nf = 0; nf < 4; nf++) {
            int c = wn * 32 + nf * 8 + r2;
            float v0 = acc[mf][nf][0] + bv0;
            float v1 = acc[mf][nf][1] + bv0;
            float v2 = acc[mf][nf][2] + bv1;
            float v3 = acc[mf][nf][3] + bv1;
            if (SILU) {
                v0 = v0 / (1.f + expf(-v0));
                v1 = v1 / (1.f + expf(-v1));
                v2 = v2 / (1.f + expf(-v2));
                v3 = v3 / (1.f + expf(-v3));
            }
            if (RES) {
                float2 r0 = *(const float2*)(y0 + c);
                float2 r1 = *(const float2*)(y1 + c);
                v0 += r0.x; v1 += r0.y; v2 += r1.x; v3 += r1.y;
            }
            *(float2*)(y0 + c) = make_float2(v0, v1);
            *(float2*)(y1 + c) = make_float2(v2, v3);
        }
    }
}

// ---------------------------------------------------------------------------
// 256-point radix-2 DIT FFT in shared memory
// ---------------------------------------------------------------------------
template <bool INV>
__device__ __forceinline__ void fft256(float2* s, int tid) {
#pragma unroll
    for (int st = 1; st <= 8; st++) {
        const int half = 1 << (st - 1);
        int p = tid & (half - 1);
        int i = ((tid >> (st - 1)) << st) | p;
        float2 w = g_tw[half + p];
        float wx = w.x;
        float wy = INV ? -w.y : w.y;
        float2 u = s[i], v = s[i + half];
        float tr = v.x * wx - v.y * wy;
        float ti = v.x * wy + v.y * wx;
        s[i]        = make_float2(u.x + tr, u.y + ti);
        s[i + half] = make_float2(u.x - tr, u.y - ti);
        __syncthreads();
    }
}
__device__ __forceinline__ int brev8(int i) { return __brev(i) >> 24; }

__global__ __launch_bounds__(128) void fft_rows_fwd(const float* __restrict__ in,
                                                    float2* __restrict__ out) {
    __shared__ float  rb[256];
    __shared__ float2 s[256];
    int tid = threadIdx.x;
    size_t img = blockIdx.y;
    int y = blockIdx.x;
    const float* src = in + (img << 16) + (y << 8);
    rb[tid] = src[tid];
    rb[tid + 128] = src[tid + 128];
    __syncthreads();
    s[tid]       = make_float2(rb[brev8(tid)], 0.f);
    s[tid + 128] = make_float2(rb[brev8(tid + 128)], 0.f);
    __syncthreads();
    fft256<false>(s, tid);
    float2* dst = out + img * (256 * WH) + (size_t)y * WH;
    for (int k = tid; k < WH; k += 128) dst[k] = s[k];
}

__global__ __launch_bounds__(128) void fft_cols_filter(float2* __restrict__ data,
                                                       const float* __restrict__ mags,
                                                       const float* __restrict__ phs) {
    __shared__ float2 sp[256];
    __shared__ float2 s[256];
    int tid = threadIdx.x;
    int kx = blockIdx.x;
    size_t img = blockIdx.y;
    int c = (int)(img & 127);
    float2* col = data + img * (256 * WH) + kx;
    sp[tid]       = col[(size_t)tid * WH];
    sp[tid + 128] = col[(size_t)(tid + 128) * WH];
    __syncthreads();
    s[tid]       = sp[brev8(tid)];
    s[tid + 128] = sp[brev8(tid + 128)];
    __syncthreads();
    fft256<false>(s, tid);
#pragma unroll
    for (int it = 0; it < 2; it++) {
        int idx = tid + it * 128;
        int kyab = (idx < 128) ? idx : 256 - idx;
        float2 v;
        if (kx * kx + kyab * kyab <= 16384) {
            int off = (c * 256 + idx) * WH + kx;
            float sg = 1.f / (1.f + expf(-mags[off])) * (1.f / 65536.f);
            float sn, cs;
            sincosf(phs[off], &sn, &cs);
            float fr = sg * cs, fi = sg * sn;
            float2 u = s[idx];
            v = make_float2(u.x * fr - u.y * fi, u.x * fi + u.y * fr);
        } else {
            v = make_float2(0.f, 0.f);
        }
        sp[idx] = v;
    }
    __syncthreads();
    s[tid]       = sp[brev8(tid)];
    s[tid + 128] = sp[brev8(tid + 128)];
    __syncthreads();
    fft256<true>(s, tid);
    col[(size_t)tid * WH]         = s[tid];
    col[(size_t)(tid + 128) * WH] = s[tid + 128];
}

__global__ __launch_bounds__(128) void fft_rows_inv(const float2* __restrict__ in,
                                                    float* __restrict__ out) {
    __shared__ float2 sp[256];
    __shared__ float2 s[256];
    int tid = threadIdx.x;
    size_t img = blockIdx.y;
    int y = blockIdx.x;
    const float2* src = in + img * (256 * WH) + (size_t)y * WH;
    for (int k = tid; k < WH; k += 128) sp[k] = src[k];
    __syncthreads();
    int r0 = brev8(tid), r1 = brev8(tid + 128);
    float2 e0 = (r0 <= 128) ? sp[r0] : make_float2(sp[256 - r0].x, -sp[256 - r0].y);
    float2 e1 = (r1 <= 128) ? sp[r1] : make_float2(sp[256 - r1].x, -sp[256 - r1].y);
    s[tid] = e0;
    s[tid + 128] = e1;
    __syncthreads();
    fft256<true>(s, tid);
    float* dst = out + (img << 16) + (y << 8);
    dst[tid]       = s[tid].x;
    dst[tid + 128] = s[tid + 128].x;
}

// ---------------------------------------------------------------------------
// Launch
// ---------------------------------------------------------------------------
extern "C" void kernel_launch(void* const* d_in, const int* in_sizes, int n_in,
                              void* d_out, int out_size) {
    const float* x   = (const float*)d_in[0];
    const float* ew  = (const float*)d_in[1];
    const float* eb  = (const float*)d_in[2];
    const float* pos = (const float*)d_in[3];
    const float* w1  = (const float*)d_in[4];
    const float* b1  = (const float*)d_in[5];
    const float* w2  = (const float*)d_in[6];
    const float* b2  = (const float*)d_in[7];
    const float* mg  = (const float*)d_in[8];
    const float* ph  = (const float*)d_in[9];
    const float* ow  = (const float*)d_in[10];
    const float* ob  = (const float*)d_in[11];
    const float* dw  = (const float*)d_in[12];
    const float* db  = (const float*)d_in[13];
    float* out = (float*)d_out;

    void *vh, *vy, *vx, *vf;
    cudaGetSymbolAddress(&vh, g_h);
    cudaGetSymbolAddress(&vy, g_y1);
    cudaGetSymbolAddress(&vx, g_x1);
    cudaGetSymbolAddress(&vf, g_fft);
    float*  H  = (float*)vh;
    float*  Y1 = (float*)vy;
    float*  X1 = (float*)vx;
    float2* FT = (float2*)vf;

    cudaFuncSetAttribute(tc_gemm<true, false>,
                         cudaFuncAttributeMaxDynamicSharedMemorySize, SM_TOTAL);
    cudaFuncSetAttribute(tc_gemm<false, false>,
                         cudaFuncAttributeMaxDynamicSharedMemorySize, SM_TOTAL);
    cudaFuncSetAttribute(tc_gemm<false, true>,
                         cudaFuncAttributeMaxDynamicSharedMemorySize, SM_TOTAL);

    init_tw_kernel<<<1, 256>>>();
    encode_kernel<<<(BATCH * DIM * NPOS) / 256, 256>>>(x, ew, eb, pos);

    const int specStride = DIM * 256 * WH;
    for (int l = 0; l < LAYERS; l++) {
        // mlp: h -> 512 (SiLU) -> 128
        tc_gemm<true, false><<<dim3(512, 4, 4), 256, SM_TOTAL>>>(
            w1 + (size_t)l * HID * DIM, b1 + l * HID, H, Y1, DIM);
        tc_gemm<false, false><<<dim3(512, 1, 4), 256, SM_TOTAL>>>(
            w2 + (size_t)l * DIM * HID, b2 + l * DIM, Y1, X1, HID);
        // spectral conv
        fft_rows_fwd<<<dim3(256, BATCH * DIM), 128>>>(X1, FT);
        fft_cols_filter<<<dim3(WH, BATCH * DIM), 128>>>(
            FT, mg + (size_t)l * specStride, ph + (size_t)l * specStride);
        fft_rows_inv<<<dim3(256, BATCH * DIM), 128>>>(FT, X1);
        // oxo conv + residual into h
        tc_gemm<false, true><<<dim3(512, 1, 4), 256, SM_TOTAL>>>(
            ow + (size_t)l * DIM * DIM, ob + l * DIM, X1, H, DIM);
    }

    decode_kernel<<<(BATCH * NPOS) / 256, 256>>>(dw, db, out);
}